// round 15
// baseline (speedup 1.0000x reference)
#include <cuda_runtime.h>
#include <cstdint>

#define BB 64
#define PP 1024
#define TT 1024
#define NITER 50
#define HALFP 512      // p-rows per cluster CTA

#define MAGIC  8388608.0f     // 2^23
#define KSCALE (1.0f / 4095.0f)

// 12-bit fixed-point Gibbs kernel q = round(4095*K), planar:
//   g_Klb : low 8 bits  (1 B/elem, 67 MB)
//   g_Ktn : top 4 bits  (packed nibbles, 33.6 MB)
// Total 100.7 MB -> L2-resident (126 MB).
__device__ __align__(16) unsigned char g_Klb[(size_t)BB * PP * TT];
__device__ __align__(16) unsigned char g_Ktn[(size_t)BB * PP * TT / 2];
__device__ __align__(16) float g_u[BB * PP];
__device__ __align__(16) float g_v[BB * TT];

// K = exp(-C/reg) -> 12-bit planes, 8 elems/thread.
__global__ void k_exp(const float* __restrict__ C, const float* __restrict__ reg) {
    const size_t i8 = (size_t)blockIdx.x * 256 + threadIdx.x;
    const float ninv = -1.0f / reg[0];
    const float4* __restrict__ C4 = (const float4*)C;
    const float4 a = C4[2 * i8];
    const float4 c = C4[2 * i8 + 1];
    unsigned int q[8];
    q[0] = __float2uint_rn(__expf(a.x * ninv) * 4095.0f);
    q[1] = __float2uint_rn(__expf(a.y * ninv) * 4095.0f);
    q[2] = __float2uint_rn(__expf(a.z * ninv) * 4095.0f);
    q[3] = __float2uint_rn(__expf(a.w * ninv) * 4095.0f);
    q[4] = __float2uint_rn(__expf(c.x * ninv) * 4095.0f);
    q[5] = __float2uint_rn(__expf(c.y * ninv) * 4095.0f);
    q[6] = __float2uint_rn(__expf(c.z * ninv) * 4095.0f);
    q[7] = __float2uint_rn(__expf(c.w * ninv) * 4095.0f);
    uint2 lb;
    lb.x = (q[0] & 255u) | ((q[1] & 255u) << 8) | ((q[2] & 255u) << 16) | ((q[3] & 255u) << 24);
    lb.y = (q[4] & 255u) | ((q[5] & 255u) << 8) | ((q[6] & 255u) << 16) | ((q[7] & 255u) << 24);
    unsigned int tn = (q[0] >> 8) | ((q[1] >> 8) << 4)
                    | ((q[2] >> 8) << 8)  | ((q[3] >> 8) << 12)
                    | ((q[4] >> 8) << 16) | ((q[5] >> 8) << 20)
                    | ((q[6] >> 8) << 24) | ((q[7] >> 8) << 28);
    ((uint2*)g_Klb)[i8] = lb;
    ((unsigned int*)g_Ktn)[i8] = tn;
}

// Unpack 8 elems from low-byte words w0,w1 + nibble word l -> exact floats.
__device__ __forceinline__ void unpack8(unsigned int w0, unsigned int w1,
                                        unsigned int l, float* f) {
    const unsigned int ne = l & 0x0F0F0F0Fu;
    const unsigned int no = (l >> 4) & 0x0F0F0F0Fu;
    const unsigned int t0 = __byte_perm(ne, no, 0x5140);
    const unsigned int t1 = __byte_perm(ne, no, 0x7362);
    const unsigned int a01 = __byte_perm(w0, t0, 0x5140);
    const unsigned int a23 = __byte_perm(w0, t0, 0x7362);
    const unsigned int a45 = __byte_perm(w1, t1, 0x5140);
    const unsigned int a67 = __byte_perm(w1, t1, 0x7362);
    f[0] = __uint_as_float(__byte_perm(a01, 0x4B000000u, 0x7410)) - MAGIC;
    f[1] = __uint_as_float(__byte_perm(a01, 0x4B000000u, 0x7432)) - MAGIC;
    f[2] = __uint_as_float(__byte_perm(a23, 0x4B000000u, 0x7410)) - MAGIC;
    f[3] = __uint_as_float(__byte_perm(a23, 0x4B000000u, 0x7432)) - MAGIC;
    f[4] = __uint_as_float(__byte_perm(a45, 0x4B000000u, 0x7410)) - MAGIC;
    f[5] = __uint_as_float(__byte_perm(a45, 0x4B000000u, 0x7432)) - MAGIC;
    f[6] = __uint_as_float(__byte_perm(a67, 0x4B000000u, 0x7410)) - MAGIC;
    f[7] = __uint_as_float(__byte_perm(a67, 0x4B000000u, 0x7432)) - MAGIC;
}

// Persistent fused Sinkhorn, cluster of 2 CTAs per batch (128 CTAs).
// One pass over 12-bit K per iteration; L2-resident; row-double-buffered
// loads to hide L2 latency within each warp.
__global__ void __launch_bounds__(512, 1) __cluster_dims__(2, 1, 1)
k_sinkhorn(const float* __restrict__ pred, const float* __restrict__ tgt) {
    __shared__ float v_s[TT];             //  4 KB
    __shared__ float u_s[HALFP];          //  2 KB
    __shared__ float buf[8][TT];          // 32 KB warp-combine tree
    __shared__ float part_peer[2][TT];    //  8 KB DSMEM partials (parity)
    __shared__ float pred_s[HALFP];       //  2 KB

    const int tid  = threadIdx.x;
    const int b    = blockIdx.x >> 1;
    const int r    = blockIdx.x & 1;
    const int peer = r ^ 1;
    const int wid  = tid >> 5;
    const int lane = tid & 31;

    pred_s[tid] = pred[b * PP + r * HALFP + tid];
    const float tgt_a = tgt[b * TT + tid];
    const float tgt_b = tgt[b * TT + tid + 512];
    __syncthreads();

    const uint4* __restrict__ LB4 =
        (const uint4*)(g_Klb + ((size_t)b * PP + (size_t)r * HALFP) * TT);
    const uint2* __restrict__ TN2 =
        (const uint2*)(g_Ktn + ((size_t)b * PP + (size_t)r * HALFP) * (TT / 2));
    const size_t row0 = (size_t)(wid * 32) * 64;

    for (int iter = 0; iter <= NITER; iter++) {
        // v into registers: vreg[j] = v[16*lane+j], vreg[16+j] = v[512+16*lane+j]
        float vreg[32];
        if (iter > 0) {
            const float4* __restrict__ vs4 = (const float4*)v_s;
#pragma unroll
            for (int i = 0; i < 4; i++) {
                const float4 va = vs4[4 * lane + i];
                vreg[4*i+0]=va.x; vreg[4*i+1]=va.y; vreg[4*i+2]=va.z; vreg[4*i+3]=va.w;
                const float4 vb = vs4[128 + 4 * lane + i];
                vreg[16+4*i+0]=vb.x; vreg[16+4*i+1]=vb.y; vreg[16+4*i+2]=vb.z; vreg[16+4*i+3]=vb.w;
            }
        }

        float acc[32];
#pragma unroll
        for (int j = 0; j < 32; j++) acc[j] = 0.0f;

        // prefetch row 0 (2x uint4 + 2x uint2 = 12 regs)
        uint4 ha = LB4[row0 + lane];
        uint4 hb = LB4[row0 + lane + 32];
        uint2 la = TN2[row0 + lane];
        uint2 lb = TN2[row0 + lane + 32];

#pragma unroll 1
        for (int rr = 0; rr < 32; rr++) {
            uint4 nha, nhb; uint2 nla, nlb;
            if (rr < 31) {
                const size_t nrw = row0 + (size_t)(rr + 1) * 64;
                nha = LB4[nrw + lane];
                nhb = LB4[nrw + lane + 32];
                nla = TN2[nrw + lane];
                nlb = TN2[nrw + lane + 32];
            }

            float f[32];
            unpack8(ha.x, ha.y, la.x, f + 0);
            unpack8(ha.z, ha.w, la.y, f + 8);
            unpack8(hb.x, hb.y, lb.x, f + 16);
            unpack8(hb.z, hb.w, lb.y, f + 24);

            if (iter == 0) {
#pragma unroll
                for (int j = 0; j < 32; j++)
                    acc[j] += f[j];
            } else {
                float a0 = 0.f, a1 = 0.f;
#pragma unroll
                for (int j = 0; j < 16; j++) {
                    a0 += f[j]      * vreg[j];
                    a1 += f[j + 16] * vreg[j + 16];
                }
                float a = a0 + a1;
#pragma unroll
                for (int o = 16; o; o >>= 1)
                    a += __shfl_xor_sync(0xFFFFFFFFu, a, o);

                const int p = wid * 32 + rr;
                const float up = __fdividef(pred_s[p], a * KSCALE);
                if (iter == NITER && lane == 0) u_s[p] = up;

#pragma unroll
                for (int j = 0; j < 32; j++)
                    acc[j] += up * f[j];
            }
            ha = nha;  hb = nhb;  la = nla;  lb = nlb;
        }

        // combine 16 warps -> buf[8][TT] (two rounds)
        if (wid < 8) {
            float4* __restrict__ dst4 = (float4*)&buf[wid][0];
#pragma unroll
            for (int i = 0; i < 4; i++) {
                dst4[4 * lane + i]       = make_float4(acc[4*i+0], acc[4*i+1], acc[4*i+2], acc[4*i+3]);
                dst4[128 + 4 * lane + i] = make_float4(acc[16+4*i+0], acc[16+4*i+1], acc[16+4*i+2], acc[16+4*i+3]);
            }
        }
        __syncthreads();
        if (wid >= 8) {
            float4* __restrict__ dst4 = (float4*)&buf[wid - 8][0];
#pragma unroll
            for (int i = 0; i < 4; i++) {
                float4 x = dst4[4 * lane + i];
                x.x += acc[4*i+0]; x.y += acc[4*i+1]; x.z += acc[4*i+2]; x.w += acc[4*i+3];
                dst4[4 * lane + i] = x;
                float4 y = dst4[128 + 4 * lane + i];
                y.x += acc[16+4*i+0]; y.y += acc[16+4*i+1]; y.z += acc[16+4*i+2]; y.w += acc[16+4*i+3];
                dst4[128 + 4 * lane + i] = y;
            }
        }
        __syncthreads();

        float s0 = 0.0f, s1 = 0.0f;
#pragma unroll
        for (int k = 0; k < 8; k++) {
            s0 += buf[k][tid];
            s1 += buf[k][tid + 512];
        }

        // DSMEM exchange with peer CTA (parity double-buffer)
        const int par = iter & 1;
        {
            unsigned int l0 = (unsigned int)__cvta_generic_to_shared(&part_peer[par][tid]);
            unsigned int l1 = (unsigned int)__cvta_generic_to_shared(&part_peer[par][tid + 512]);
            unsigned int r0, r1;
            asm volatile("mapa.shared::cluster.u32 %0, %1, %2;" : "=r"(r0) : "r"(l0), "r"(peer));
            asm volatile("mapa.shared::cluster.u32 %0, %1, %2;" : "=r"(r1) : "r"(l1), "r"(peer));
            asm volatile("st.shared::cluster.f32 [%0], %1;" :: "r"(r0), "f"(s0) : "memory");
            asm volatile("st.shared::cluster.f32 [%0], %1;" :: "r"(r1), "f"(s1) : "memory");
        }
        asm volatile("barrier.cluster.arrive.aligned;" ::: "memory");
        asm volatile("barrier.cluster.wait.aligned;" ::: "memory");

        v_s[tid]       = tgt_a / ((s0 + part_peer[par][tid]) * KSCALE);
        v_s[tid + 512] = tgt_b / ((s1 + part_peer[par][tid + 512]) * KSCALE);
        __syncthreads();
    }

    g_u[b * PP + r * HALFP + tid] = u_s[tid];
    if (r == 0) {
        g_v[b * TT + tid]       = v_s[tid];
        g_v[b * TT + tid + 512] = v_s[tid + 512];
    }
}

// Final: P = u * exp(-C/reg) * v recomputed in fp32 from C.
__global__ void k_final(const float* __restrict__ C, const float* __restrict__ reg,
                        float* __restrict__ out) {
    const size_t i4 = (size_t)blockIdx.x * 256 + threadIdx.x;
    const float ninv = -1.0f / reg[0];
    const int row = (int)((i4 * 4) >> 10);
    const int b   = row >> 10;
    const int t4  = (int)(i4 & 255);

    const float  u = g_u[row];
    const float4 c = ((const float4*)C)[i4];
    const float4 v = ((const float4*)(g_v + b * TT))[t4];

    float4 rv;
    rv.x = u * __expf(c.x * ninv) * v.x;
    rv.y = u * __expf(c.y * ninv) * v.y;
    rv.z = u * __expf(c.z * ninv) * v.z;
    rv.w = u * __expf(c.w * ninv) * v.w;
    ((float4*)out)[i4] = rv;
}

extern "C" void kernel_launch(void* const* d_in, const int* in_sizes, int n_in,
                              void* d_out, int out_size) {
    const float* pred = (const float*)d_in[0];
    const float* tgt  = (const float*)d_in[1];
    const float* C    = (const float*)d_in[2];
    const float* reg  = (const float*)d_in[3];
    float* out = (float*)d_out;

    const int n8 = (BB * PP * TT) / 8;
    const int n4 = (BB * PP * TT) / 4;

    k_exp<<<n8 / 256, 256>>>(C, reg);
    k_sinkhorn<<<2 * BB, 512>>>(pred, tgt);
    k_final<<<n4 / 256, 256>>>(C, reg, out);
}

// round 17
// speedup vs baseline: 1.0669x; 1.0669x over previous
#include <cuda_runtime.h>
#include <cstdint>

#define BB 64
#define PP 1024
#define TT 1024
#define NITER 50
#define HALFP 512      // p-rows per cluster CTA

#define MAGIC  8388608.0f     // 2^23
#define QMAX   4095.0f

// 12-bit fixed-point Gibbs kernel q = round(4095*K), planar:
//   g_Klb : low 8 bits  (1 B/elem, 67 MB)
//   g_Ktn : top 4 bits  (packed nibbles, 33.6 MB)
// Total 100.7 MB -> L2-resident (126 MB).
__device__ __align__(16) unsigned char g_Klb[(size_t)BB * PP * TT];
__device__ __align__(16) unsigned char g_Ktn[(size_t)BB * PP * TT / 2];
__device__ __align__(16) float g_u[BB * PP];
__device__ __align__(16) float g_v[BB * TT];

// Warp sum via xor-butterfly (sm_103 has no redux.f32).
__device__ __forceinline__ float warp_sum(float x) {
#pragma unroll
    for (int o = 16; o; o >>= 1)
        x += __shfl_xor_sync(0xFFFFFFFFu, x, o);
    return x;
}

// K = exp(-C/reg) -> 12-bit planes, 8 elems/thread.
__global__ void k_exp(const float* __restrict__ C, const float* __restrict__ reg) {
    const size_t i8 = (size_t)blockIdx.x * 256 + threadIdx.x;
    const float ninv = -1.0f / reg[0];
    const float4* __restrict__ C4 = (const float4*)C;
    const float4 a = C4[2 * i8];
    const float4 c = C4[2 * i8 + 1];
    unsigned int q[8];
    q[0] = __float2uint_rn(__expf(a.x * ninv) * QMAX);
    q[1] = __float2uint_rn(__expf(a.y * ninv) * QMAX);
    q[2] = __float2uint_rn(__expf(a.z * ninv) * QMAX);
    q[3] = __float2uint_rn(__expf(a.w * ninv) * QMAX);
    q[4] = __float2uint_rn(__expf(c.x * ninv) * QMAX);
    q[5] = __float2uint_rn(__expf(c.y * ninv) * QMAX);
    q[6] = __float2uint_rn(__expf(c.z * ninv) * QMAX);
    q[7] = __float2uint_rn(__expf(c.w * ninv) * QMAX);
    uint2 lb;
    lb.x = (q[0] & 255u) | ((q[1] & 255u) << 8) | ((q[2] & 255u) << 16) | ((q[3] & 255u) << 24);
    lb.y = (q[4] & 255u) | ((q[5] & 255u) << 8) | ((q[6] & 255u) << 16) | ((q[7] & 255u) << 24);
    unsigned int tn = (q[0] >> 8) | ((q[1] >> 8) << 4)
                    | ((q[2] >> 8) << 8)  | ((q[3] >> 8) << 12)
                    | ((q[4] >> 8) << 16) | ((q[5] >> 8) << 20)
                    | ((q[6] >> 8) << 24) | ((q[7] >> 8) << 28);
    ((uint2*)g_Klb)[i8] = lb;
    ((unsigned int*)g_Ktn)[i8] = tn;
}

// Unpack 8 elems from low-byte words w0,w1 + nibble word l -> exact floats.
__device__ __forceinline__ void unpack8(unsigned int w0, unsigned int w1,
                                        unsigned int l, float* f) {
    const unsigned int ne = l & 0x0F0F0F0Fu;
    const unsigned int no = (l >> 4) & 0x0F0F0F0Fu;
    const unsigned int t0 = __byte_perm(ne, no, 0x5140);
    const unsigned int t1 = __byte_perm(ne, no, 0x7362);
    const unsigned int a01 = __byte_perm(w0, t0, 0x5140);
    const unsigned int a23 = __byte_perm(w0, t0, 0x7362);
    const unsigned int a45 = __byte_perm(w1, t1, 0x5140);
    const unsigned int a67 = __byte_perm(w1, t1, 0x7362);
    f[0] = __uint_as_float(__byte_perm(a01, 0x4B000000u, 0x7410)) - MAGIC;
    f[1] = __uint_as_float(__byte_perm(a01, 0x4B000000u, 0x7432)) - MAGIC;
    f[2] = __uint_as_float(__byte_perm(a23, 0x4B000000u, 0x7410)) - MAGIC;
    f[3] = __uint_as_float(__byte_perm(a23, 0x4B000000u, 0x7432)) - MAGIC;
    f[4] = __uint_as_float(__byte_perm(a45, 0x4B000000u, 0x7410)) - MAGIC;
    f[5] = __uint_as_float(__byte_perm(a45, 0x4B000000u, 0x7432)) - MAGIC;
    f[6] = __uint_as_float(__byte_perm(a67, 0x4B000000u, 0x7410)) - MAGIC;
    f[7] = __uint_as_float(__byte_perm(a67, 0x4B000000u, 0x7432)) - MAGIC;
}

// Persistent fused Sinkhorn, cluster of 2 CTAs per batch (128 CTAs).
// One pass over 12-bit K per iteration; L2-resident; row-double-buffered
// loads; unroll-2 row loop so ptxas can hide each row's shuffle-reduce
// latency under the neighbor row's unpack/dot instructions.
__global__ void __launch_bounds__(512, 1) __cluster_dims__(2, 1, 1)
k_sinkhorn(const float* __restrict__ pred, const float* __restrict__ tgt) {
    __shared__ float v_s[TT];             //  4 KB
    __shared__ float u_s[HALFP];          //  2 KB
    __shared__ float buf[8][TT];          // 32 KB warp-combine tree
    __shared__ float part_peer[2][TT];    //  8 KB DSMEM partials (parity)
    __shared__ float pred_s[HALFP];       //  2 KB

    const int tid  = threadIdx.x;
    const int b    = blockIdx.x >> 1;
    const int r    = blockIdx.x & 1;
    const int peer = r ^ 1;
    const int wid  = tid >> 5;
    const int lane = tid & 31;

    pred_s[tid] = pred[b * PP + r * HALFP + tid] * QMAX;   // fold 1/4095
    const float tgt_a = tgt[b * TT + tid] * QMAX;
    const float tgt_b = tgt[b * TT + tid + 512] * QMAX;
    __syncthreads();

    const uint4* __restrict__ LB4 =
        (const uint4*)(g_Klb + ((size_t)b * PP + (size_t)r * HALFP) * TT);
    const uint2* __restrict__ TN2 =
        (const uint2*)(g_Ktn + ((size_t)b * PP + (size_t)r * HALFP) * (TT / 2));
    const size_t row0 = (size_t)(wid * 32) * 64;

    for (int iter = 0; iter <= NITER; iter++) {
        // v into registers: vreg[j] = v[16*lane+j], vreg[16+j] = v[512+16*lane+j]
        float vreg[32];
        if (iter > 0) {
            const float4* __restrict__ vs4 = (const float4*)v_s;
#pragma unroll
            for (int i = 0; i < 4; i++) {
                const float4 va = vs4[4 * lane + i];
                vreg[4*i+0]=va.x; vreg[4*i+1]=va.y; vreg[4*i+2]=va.z; vreg[4*i+3]=va.w;
                const float4 vb = vs4[128 + 4 * lane + i];
                vreg[16+4*i+0]=vb.x; vreg[16+4*i+1]=vb.y; vreg[16+4*i+2]=vb.z; vreg[16+4*i+3]=vb.w;
            }
        }

        float acc[32];
#pragma unroll
        for (int j = 0; j < 32; j++) acc[j] = 0.0f;

        // prefetch row 0 (2x uint4 + 2x uint2 = 12 regs)
        uint4 ha = LB4[row0 + lane];
        uint4 hb = LB4[row0 + lane + 32];
        uint2 la = TN2[row0 + lane];
        uint2 lb = TN2[row0 + lane + 32];

#pragma unroll 2
        for (int rr = 0; rr < 32; rr++) {
            uint4 nha, nhb; uint2 nla, nlb;
            if (rr < 31) {
                const size_t nrw = row0 + (size_t)(rr + 1) * 64;
                nha = LB4[nrw + lane];
                nhb = LB4[nrw + lane + 32];
                nla = TN2[nrw + lane];
                nlb = TN2[nrw + lane + 32];
            }

            float f[32];
            unpack8(ha.x, ha.y, la.x, f + 0);
            unpack8(ha.z, ha.w, la.y, f + 8);
            unpack8(hb.x, hb.y, lb.x, f + 16);
            unpack8(hb.z, hb.w, lb.y, f + 24);

            if (iter == 0) {
#pragma unroll
                for (int j = 0; j < 32; j++)
                    acc[j] += f[j];
            } else {
                float a0 = 0.f, a1 = 0.f;
#pragma unroll
                for (int j = 0; j < 16; j++) {
                    a0 += f[j]      * vreg[j];
                    a1 += f[j + 16] * vreg[j + 16];
                }
                const float a = warp_sum(a0 + a1);

                const int p = wid * 32 + rr;
                const float up = __fdividef(pred_s[p], a);
                if (iter == NITER && lane == 0) u_s[p] = up;

#pragma unroll
                for (int j = 0; j < 32; j++)
                    acc[j] += up * f[j];
            }
            ha = nha;  hb = nhb;  la = nla;  lb = nlb;
        }

        // combine 16 warps -> buf[8][TT] (two rounds)
        if (wid < 8) {
            float4* __restrict__ dst4 = (float4*)&buf[wid][0];
#pragma unroll
            for (int i = 0; i < 4; i++) {
                dst4[4 * lane + i]       = make_float4(acc[4*i+0], acc[4*i+1], acc[4*i+2], acc[4*i+3]);
                dst4[128 + 4 * lane + i] = make_float4(acc[16+4*i+0], acc[16+4*i+1], acc[16+4*i+2], acc[16+4*i+3]);
            }
        }
        __syncthreads();
        if (wid >= 8) {
            float4* __restrict__ dst4 = (float4*)&buf[wid - 8][0];
#pragma unroll
            for (int i = 0; i < 4; i++) {
                float4 x = dst4[4 * lane + i];
                x.x += acc[4*i+0]; x.y += acc[4*i+1]; x.z += acc[4*i+2]; x.w += acc[4*i+3];
                dst4[4 * lane + i] = x;
                float4 y = dst4[128 + 4 * lane + i];
                y.x += acc[16+4*i+0]; y.y += acc[16+4*i+1]; y.z += acc[16+4*i+2]; y.w += acc[16+4*i+3];
                dst4[128 + 4 * lane + i] = y;
            }
        }
        __syncthreads();

        float s0 = 0.0f, s1 = 0.0f;
#pragma unroll
        for (int k = 0; k < 8; k++) {
            s0 += buf[k][tid];
            s1 += buf[k][tid + 512];
        }

        // DSMEM exchange with peer CTA (parity double-buffer)
        const int par = iter & 1;
        {
            unsigned int l0 = (unsigned int)__cvta_generic_to_shared(&part_peer[par][tid]);
            unsigned int l1 = (unsigned int)__cvta_generic_to_shared(&part_peer[par][tid + 512]);
            unsigned int r0, r1;
            asm volatile("mapa.shared::cluster.u32 %0, %1, %2;" : "=r"(r0) : "r"(l0), "r"(peer));
            asm volatile("mapa.shared::cluster.u32 %0, %1, %2;" : "=r"(r1) : "r"(l1), "r"(peer));
            asm volatile("st.shared::cluster.f32 [%0], %1;" :: "r"(r0), "f"(s0) : "memory");
            asm volatile("st.shared::cluster.f32 [%0], %1;" :: "r"(r1), "f"(s1) : "memory");
        }
        asm volatile("barrier.cluster.arrive.aligned;" ::: "memory");
        asm volatile("barrier.cluster.wait.aligned;" ::: "memory");

        v_s[tid]       = tgt_a / (s0 + part_peer[par][tid]);
        v_s[tid + 512] = tgt_b / (s1 + part_peer[par][tid + 512]);
        __syncthreads();
    }

    g_u[b * PP + r * HALFP + tid] = u_s[tid];
    if (r == 0) {
        g_v[b * TT + tid]       = v_s[tid];
        g_v[b * TT + tid + 512] = v_s[tid + 512];
    }
}

// Final: P = u * exp(-C/reg) * v recomputed in fp32 from C.
__global__ void k_final(const float* __restrict__ C, const float* __restrict__ reg,
                        float* __restrict__ out) {
    const size_t i4 = (size_t)blockIdx.x * 256 + threadIdx.x;
    const float ninv = -1.0f / reg[0];
    const int row = (int)((i4 * 4) >> 10);
    const int b   = row >> 10;
    const int t4  = (int)(i4 & 255);

    const float  u = g_u[row];
    const float4 c = ((const float4*)C)[i4];
    const float4 v = ((const float4*)(g_v + b * TT))[t4];

    float4 rv;
    rv.x = u * __expf(c.x * ninv) * v.x;
    rv.y = u * __expf(c.y * ninv) * v.y;
    rv.z = u * __expf(c.z * ninv) * v.z;
    rv.w = u * __expf(c.w * ninv) * v.w;
    ((float4*)out)[i4] = rv;
}

extern "C" void kernel_launch(void* const* d_in, const int* in_sizes, int n_in,
                              void* d_out, int out_size) {
    const float* pred = (const float*)d_in[0];
    const float* tgt  = (const float*)d_in[1];
    const float* C    = (const float*)d_in[2];
    const float* reg  = (const float*)d_in[3];
    float* out = (float*)d_out;

    const int n8 = (BB * PP * TT) / 8;
    const int n4 = (BB * PP * TT) / 4;

    k_exp<<<n8 / 256, 256>>>(C, reg);
    k_sinkhorn<<<2 * BB, 512>>>(pred, tgt);
    k_final<<<n4 / 256, 256>>>(C, reg, out);
}